// round 7
// baseline (speedup 1.0000x reference)
#include <cuda_runtime.h>
#include <cuda_fp16.h>

// Trilinear 3D grid sample, (y,z,c)-fused fp16 corner layout.
// im:      [B, X, Y, Z, C] float32, B=2, X=Y=Z=160, C=2
// defgrid: [B, X, Y, Z, 3] float32
// out:     [B, X, Y, Z, C] float32
//
// P2[b][x][y][z] = 8 halves (16B): {(y,z),(y,z+1),(y+1,z),(y+1,z+1)} x {c0,c1}.
// Each voxel: TWO divergent 16B gathers (one per x-corner), with an
// L2::evict_last cache policy (createpolicy + ld.L2::cache_hint) so the
// 65.5MB table stays L2-resident against streaming traffic (which uses .cs).
// Schedule: pre(b=0) -> [gather(b=0) || pre(b=1)] fused -> gather(b=1).

#define XD 160
#define YD 160
#define ZD 160
#define BD 2
#define VOL (XD * YD * ZD)          // 4,096,000
#define THREADS 256
#define PRE_BLOCKS (VOL / THREADS)          // 16000
#define GATHER_BLOCKS (VOL / 2 / THREADS)   // 8000

__device__ uint4 g_P2[BD][VOL];

// ---------- evict-last cache policy ----------
__device__ __forceinline__ unsigned long long make_evict_last_policy() {
    unsigned long long pol;
    asm volatile("createpolicy.fractional.L2::evict_last.b64 %0, 1.0;"
                 : "=l"(pol));
    return pol;
}

__device__ __forceinline__ uint4 ld_policy(const uint4* p, unsigned long long pol) {
    uint4 q;
    asm volatile("ld.global.nc.L2::cache_hint.v4.u32 {%0,%1,%2,%3}, [%4], %5;"
                 : "=r"(q.x), "=r"(q.y), "=r"(q.z), "=r"(q.w)
                 : "l"(p), "l"(pol));
    return q;
}

// ---------- preprocess body ----------
__device__ __forceinline__ void preprocess_body(
    const float2* __restrict__ im, int b, int i)
{
    int z = i % ZD;
    int t = i / ZD;
    int y = t % YD;

    const float2* __restrict__ imb = im + (size_t)b * VOL;

    int zp = (z < ZD - 1) ? 1 : 0;    // clamp z+1
    int yp = (y < YD - 1) ? ZD : 0;   // clamp y+1

    float2 v00 = __ldcs(&imb[i]);
    float2 v01 = __ldcs(&imb[i + zp]);
    float2 v10 = __ldcs(&imb[i + yp]);
    float2 v11 = __ldcs(&imb[i + yp + zp]);

    __half2 h00 = __float22half2_rn(v00);
    __half2 h01 = __float22half2_rn(v01);
    __half2 h10 = __float22half2_rn(v10);
    __half2 h11 = __float22half2_rn(v11);

    uint4 pk;
    pk.x = *(unsigned int*)&h00;
    pk.y = *(unsigned int*)&h01;
    pk.z = *(unsigned int*)&h10;
    pk.w = *(unsigned int*)&h11;
    g_P2[b][i] = pk;
}

__device__ __forceinline__ float2 h2f(unsigned int u) {
    __half2 h = *(__half2*)&u;
    return __half22float2(h);
}

__device__ __forceinline__ float2 interp_voxel(
    float x, float y, float z, uint4 q0, uint4 q1,
    int x0, int y0u, int z0u, int zc)
{
    // Lower-edge clip duplication (coords >= 0 so ~never taken; keeps exact
    // reference semantics).
    if (z0u < 0) { q0.y = q0.x; q0.w = q0.z; q1.y = q1.x; q1.w = q1.z; }
    if (y0u < 0) { q0.z = q0.x; q0.w = q0.y; q1.z = q1.x; q1.w = q1.y; }

    float2 Ia = h2f(q0.x), Ib = h2f(q0.y), Ic = h2f(q0.z), Id = h2f(q0.w);
    float2 Ie = h2f(q1.x), If = h2f(q1.y), Ig = h2f(q1.z), Ih = h2f(q1.w);

    int y0 = min(max(y0u, 0), YD - 1);
    const float xd = x - (float)x0;
    const float yd = y - (float)y0;
    const float zd = z - (float)zc;
    const float xm = 1.0f - xd;
    const float ym = 1.0f - yd;
    const float zm = 1.0f - zd;

    float cae0 = Ia.x * xm + Ie.x * xd;
    float cae1 = Ia.y * xm + Ie.y * xd;
    float cbf0 = Ib.x * xm + If.x * xd;
    float cbf1 = Ib.y * xm + If.y * xd;
    float ccg0 = Ic.x * xm + Ig.x * xd;
    float ccg1 = Ic.y * xm + Ig.y * xd;
    float cdh0 = Id.x * xm + Ih.x * xd;
    float cdh1 = Id.y * xm + Ih.y * xd;

    float c0_0 = cae0 * ym + ccg0 * yd;
    float c0_1 = cae1 * ym + ccg1 * yd;
    float c1_0 = cbf0 * ym + cdh0 * yd;
    float c1_1 = cbf1 * ym + cdh1 * yd;

    float2 r;
    r.x = c0_0 * zm + c1_0 * zd;
    r.y = c0_1 * zm + c1_1 * zd;
    return r;
}

// ---------- gather body: one voxel-pair ----------
__device__ __forceinline__ void gather_body(
    const float* __restrict__ defgrid,
    float4* __restrict__ out, int b, int t)
{
    int i  = t * 2;
    int gi = b * VOL + i;

    const float2* dg = (const float2*)(defgrid + (size_t)3 * gi);
    float2 d0 = __ldcs(dg + 0);   // xA, yA
    float2 d1 = __ldcs(dg + 1);   // zA, xB
    float2 d2 = __ldcs(dg + 2);   // yB, zB

    const float xA = d0.x, yA = d0.y, zA = d1.x;
    const float xB = d1.y, yB = d2.x, zB = d2.y;

    int xA0u = (int)floorf(xA), yA0u = (int)floorf(yA), zA0u = (int)floorf(zA);
    int xA0 = min(max(xA0u, 0), XD - 1);
    int xA1 = min(max(xA0u + 1, 0), XD - 1);
    int yA0 = min(max(yA0u, 0), YD - 1);
    int zAc = min(max(zA0u, 0), ZD - 1);

    int xB0u = (int)floorf(xB), yB0u = (int)floorf(yB), zB0u = (int)floorf(zB);
    int xB0 = min(max(xB0u, 0), XD - 1);
    int xB1 = min(max(xB0u + 1, 0), XD - 1);
    int yB0 = min(max(yB0u, 0), YD - 1);
    int zBc = min(max(zB0u, 0), ZD - 1);

    const uint4* __restrict__ Pb = g_P2[b];
    unsigned long long pol = make_evict_last_policy();

    uint4 qA0 = ld_policy(&Pb[(xA0 * YD + yA0) * ZD + zAc], pol);
    uint4 qA1 = ld_policy(&Pb[(xA1 * YD + yA0) * ZD + zAc], pol);
    uint4 qB0 = ld_policy(&Pb[(xB0 * YD + yB0) * ZD + zBc], pol);
    uint4 qB1 = ld_policy(&Pb[(xB1 * YD + yB0) * ZD + zBc], pol);

    float2 rA = interp_voxel(xA, yA, zA, qA0, qA1, xA0, yA0u, zA0u, zAc);
    float2 rB = interp_voxel(xB, yB, zB, qB0, qB1, xB0, yB0u, zB0u, zBc);

    float4 o = make_float4(rA.x, rA.y, rB.x, rB.y);
    __stcs(&out[gi / 2], o);
}

// ---------- kernels ----------
__global__ __launch_bounds__(THREADS) void preprocess_kernel(
    const float2* __restrict__ im, int b)
{
    int i = blockIdx.x * THREADS + threadIdx.x;
    if (i < VOL) preprocess_body(im, b, i);
}

__global__ __launch_bounds__(THREADS) void gather_kernel(
    const float* __restrict__ defgrid,
    float4* __restrict__ out, int b)
{
    int t = blockIdx.x * THREADS + threadIdx.x;
    if (t < VOL / 2) gather_body(defgrid, out, b, t);
}

// Fused: gather(b=0) runs on 1/3 of blocks, preprocess(b=1) on 2/3,
// interleaved so both are co-resident (complementary bottlenecks:
// gather = L1 wavefronts, preprocess = DRAM).
__global__ __launch_bounds__(THREADS) void fused_kernel(
    const float2* __restrict__ im,
    const float* __restrict__ defgrid,
    float4* __restrict__ out)
{
    int bx = blockIdx.x;            // 0 .. 3*GATHER_BLOCKS-1 (= 24000)
    int k  = bx / 3;
    int r  = bx - 3 * k;
    if (r == 0) {
        // gather block k for batch 0
        int t = k * THREADS + threadIdx.x;
        if (t < VOL / 2) gather_body(defgrid, out, 0, t);
    } else {
        // preprocess block (2k + r-1) for batch 1
        int pb = 2 * k + (r - 1);   // 0 .. 15999
        int i  = pb * THREADS + threadIdx.x;
        if (i < VOL) preprocess_body(im, 1, i);
    }
}

extern "C" void kernel_launch(void* const* d_in, const int* in_sizes, int n_in,
                              void* d_out, int out_size)
{
    const float2* im     = (const float2*)d_in[0];
    const float* defgrid = (const float*)d_in[1];
    float4* out          = (float4*)d_out;

    preprocess_kernel<<<PRE_BLOCKS, THREADS>>>(im, 0);
    fused_kernel<<<3 * GATHER_BLOCKS, THREADS>>>(im, defgrid, out);
    gather_kernel<<<GATHER_BLOCKS, THREADS>>>(defgrid, out, 1);
}

// round 8
// speedup vs baseline: 1.0137x; 1.0137x over previous
#include <cuda_runtime.h>
#include <cuda_fp16.h>

// Trilinear 3D grid sample, (y,z,c)-fused fp16 corner layout.
// im:      [B, X, Y, Z, C] float32, B=2, X=Y=Z=160, C=2
// defgrid: [B, X, Y, Z, 3] float32
// out:     [B, X, Y, Z, C] float32
//
// P2[b][x][y][z] = 8 halves (16B): {(y,z),(y,z+1),(y+1,z),(y+1,z+1)} x {c0,c1}.
// Each voxel: TWO divergent 16B gathers (one per x-corner) with an
// L2::evict_last cache policy so the 65.5MB table stays L2-resident;
// streaming traffic (defgrid/out/im) uses evict-first (.cs).
// SEQUENTIAL schedule (overlap thrashes L2: table0+table1 > L2 capacity):
//   pre(0) -> gather(0) -> pre(1) -> gather(1)

#define XD 160
#define YD 160
#define ZD 160
#define BD 2
#define VOL (XD * YD * ZD)          // 4,096,000
#define THREADS 256
#define PRE_BLOCKS (VOL / 2 / THREADS)      // 8000 (2 voxels/thread)
#define GATHER_BLOCKS (VOL / 2 / THREADS)   // 8000 (2 voxels/thread)

__device__ uint4 g_P2[BD][VOL];

// ---------- evict-last cache policy ----------
__device__ __forceinline__ unsigned long long make_evict_last_policy() {
    unsigned long long pol;
    asm volatile("createpolicy.fractional.L2::evict_last.b64 %0, 1.0;"
                 : "=l"(pol));
    return pol;
}

__device__ __forceinline__ uint4 ld_policy(const uint4* p, unsigned long long pol) {
    uint4 q;
    asm volatile("ld.global.nc.L2::cache_hint.v4.u32 {%0,%1,%2,%3}, [%4], %5;"
                 : "=r"(q.x), "=r"(q.y), "=r"(q.z), "=r"(q.w)
                 : "l"(p), "l"(pol));
    return q;
}

__device__ __forceinline__ unsigned int pack_h2(float a, float b) {
    __half2 h = __floats2half2_rn(a, b);
    return *(unsigned int*)&h;
}

// ---------- preprocess: 2 consecutive-z voxels per thread ----------
__global__ __launch_bounds__(THREADS) void preprocess_kernel(
    const float2* __restrict__ im, int b)
{
    int t = blockIdx.x * THREADS + threadIdx.x;
    if (t >= VOL / 2) return;

    int i = t * 2;              // even; ZD=160 even => pair stays in one z-row
    int z = i % ZD;             // even, 0..158
    int y = (i / ZD) % YD;

    const float2* __restrict__ imb = im + (size_t)b * VOL;
    int yp = (y < YD - 1) ? ZD : 0;   // clamp y+1
    int j  = i + yp;

    // row y: voxels z, z+1 (16B aligned since i even), then z+2 (clamped)
    float4 a4 = __ldcs((const float4*)(imb + i));
    float2 c  = (z + 2 < ZD) ? __ldcs(&imb[i + 2])
                             : make_float2(a4.z, a4.w);
    // row y+1
    float4 b4 = __ldcs((const float4*)(imb + j));
    float2 d  = (z + 2 < ZD) ? __ldcs(&imb[j + 2])
                             : make_float2(b4.z, b4.w);

    uint4 p0, p1;
    p0.x = pack_h2(a4.x, a4.y);   // (y  , z  )
    p0.y = pack_h2(a4.z, a4.w);   // (y  , z+1)
    p0.z = pack_h2(b4.x, b4.y);   // (y+1, z  )
    p0.w = pack_h2(b4.z, b4.w);   // (y+1, z+1)

    p1.x = p0.y;                  // (y  , z+1)
    p1.y = pack_h2(c.x, c.y);     // (y  , z+2 clamped)
    p1.z = p0.w;                  // (y+1, z+1)
    p1.w = pack_h2(d.x, d.y);     // (y+1, z+2 clamped)

    g_P2[b][i]     = p0;
    g_P2[b][i + 1] = p1;
}

__device__ __forceinline__ float2 h2f(unsigned int u) {
    __half2 h = *(__half2*)&u;
    return __half22float2(h);
}

__device__ __forceinline__ float2 interp_voxel(
    float x, float y, float z, uint4 q0, uint4 q1,
    int x0, int y0u, int z0u, int zc)
{
    // Lower-edge clip duplication (coords >= 0 so ~never taken; keeps exact
    // reference semantics).
    if (z0u < 0) { q0.y = q0.x; q0.w = q0.z; q1.y = q1.x; q1.w = q1.z; }
    if (y0u < 0) { q0.z = q0.x; q0.w = q0.y; q1.z = q1.x; q1.w = q1.y; }

    float2 Ia = h2f(q0.x), Ib = h2f(q0.y), Ic = h2f(q0.z), Id = h2f(q0.w);
    float2 Ie = h2f(q1.x), If = h2f(q1.y), Ig = h2f(q1.z), Ih = h2f(q1.w);

    int y0 = min(max(y0u, 0), YD - 1);
    const float xd = x - (float)x0;
    const float yd = y - (float)y0;
    const float zd = z - (float)zc;
    const float xm = 1.0f - xd;
    const float ym = 1.0f - yd;
    const float zm = 1.0f - zd;

    float cae0 = Ia.x * xm + Ie.x * xd;
    float cae1 = Ia.y * xm + Ie.y * xd;
    float cbf0 = Ib.x * xm + If.x * xd;
    float cbf1 = Ib.y * xm + If.y * xd;
    float ccg0 = Ic.x * xm + Ig.x * xd;
    float ccg1 = Ic.y * xm + Ig.y * xd;
    float cdh0 = Id.x * xm + Ih.x * xd;
    float cdh1 = Id.y * xm + Ih.y * xd;

    float c0_0 = cae0 * ym + ccg0 * yd;
    float c0_1 = cae1 * ym + ccg1 * yd;
    float c1_0 = cbf0 * ym + cdh0 * yd;
    float c1_1 = cbf1 * ym + cdh1 * yd;

    float2 r;
    r.x = c0_0 * zm + c1_0 * zd;
    r.y = c0_1 * zm + c1_1 * zd;
    return r;
}

__global__ __launch_bounds__(THREADS) void gather_kernel(
    const float* __restrict__ defgrid,
    float4* __restrict__ out, int b)
{
    int t = blockIdx.x * THREADS + threadIdx.x;
    if (t >= VOL / 2) return;

    int i  = t * 2;
    int gi = b * VOL + i;

    const float2* dg = (const float2*)(defgrid + (size_t)3 * gi);
    float2 d0 = __ldcs(dg + 0);   // xA, yA
    float2 d1 = __ldcs(dg + 1);   // zA, xB
    float2 d2 = __ldcs(dg + 2);   // yB, zB

    const float xA = d0.x, yA = d0.y, zA = d1.x;
    const float xB = d1.y, yB = d2.x, zB = d2.y;

    int xA0u = (int)floorf(xA), yA0u = (int)floorf(yA), zA0u = (int)floorf(zA);
    int xA0 = min(max(xA0u, 0), XD - 1);
    int xA1 = min(max(xA0u + 1, 0), XD - 1);
    int yA0 = min(max(yA0u, 0), YD - 1);
    int zAc = min(max(zA0u, 0), ZD - 1);

    int xB0u = (int)floorf(xB), yB0u = (int)floorf(yB), zB0u = (int)floorf(zB);
    int xB0 = min(max(xB0u, 0), XD - 1);
    int xB1 = min(max(xB0u + 1, 0), XD - 1);
    int yB0 = min(max(yB0u, 0), YD - 1);
    int zBc = min(max(zB0u, 0), ZD - 1);

    const uint4* __restrict__ Pb = g_P2[b];
    unsigned long long pol = make_evict_last_policy();

    uint4 qA0 = ld_policy(&Pb[(xA0 * YD + yA0) * ZD + zAc], pol);
    uint4 qA1 = ld_policy(&Pb[(xA1 * YD + yA0) * ZD + zAc], pol);
    uint4 qB0 = ld_policy(&Pb[(xB0 * YD + yB0) * ZD + zBc], pol);
    uint4 qB1 = ld_policy(&Pb[(xB1 * YD + yB0) * ZD + zBc], pol);

    float2 rA = interp_voxel(xA, yA, zA, qA0, qA1, xA0, yA0u, zA0u, zAc);
    float2 rB = interp_voxel(xB, yB, zB, qB0, qB1, xB0, yB0u, zB0u, zBc);

    float4 o = make_float4(rA.x, rA.y, rB.x, rB.y);
    __stcs(&out[gi / 2], o);
}

extern "C" void kernel_launch(void* const* d_in, const int* in_sizes, int n_in,
                              void* d_out, int out_size)
{
    const float2* im     = (const float2*)d_in[0];
    const float* defgrid = (const float*)d_in[1];
    float4* out          = (float4*)d_out;

    for (int b = 0; b < BD; b++) {
        preprocess_kernel<<<PRE_BLOCKS, THREADS>>>(im, b);
        gather_kernel<<<GATHER_BLOCKS, THREADS>>>(defgrid, out, b);
    }
}